// round 2
// baseline (speedup 1.0000x reference)
#include <cuda_runtime.h>
#include <cuda_bf16.h>

#define BATCH   16
#define CIN     256
#define COUT    256
#define HH      32
#define WW      32
#define HW      1024
#define NE      8
#define CO_TILE 8
#define CI_CHUNK 8
#define HALO    34

__device__ int g_decisions[BATCH];

// ---------------------------------------------------------------------------
// Kernel 1: global-avg-pool -> linear router -> argmax  (one block per batch)
// ---------------------------------------------------------------------------
__global__ void router_kernel(const float* __restrict__ x,
                              const float* __restrict__ wc,
                              const float* __restrict__ bc) {
    int b    = blockIdx.x;
    int tid  = threadIdx.x;
    int warp = tid >> 5;
    int lane = tid & 31;

    __shared__ float sPooled[CIN];
    __shared__ float sLog[NE];

    const float* xb = x + (size_t)b * CIN * HW;

    // Each warp reduces channels warp, warp+8, ... (coalesced within channel)
    for (int ci = warp; ci < CIN; ci += 8) {
        const float* p = xb + (size_t)ci * HW;
        float s = 0.f;
        #pragma unroll 4
        for (int k = lane; k < HW; k += 32) s += p[k];
        #pragma unroll
        for (int o = 16; o > 0; o >>= 1) s += __shfl_xor_sync(0xffffffffu, s, o);
        if (lane == 0) sPooled[ci] = s * (1.0f / HW);
    }
    __syncthreads();

    if (warp == 0) {
        if (lane < NE) {
            const float* w = wc + lane * CIN;
            float s = 0.f;
            #pragma unroll 8
            for (int k = 0; k < CIN; k++) s += sPooled[k] * w[k];
            sLog[lane] = s + bc[lane];
        }
        __syncwarp();
        if (lane == 0) {
            float best = sLog[0];
            int   bi   = 0;
            #pragma unroll
            for (int e = 1; e < NE; e++) {
                if (sLog[e] > best) { best = sLog[e]; bi = e; }
            }
            g_decisions[b] = bi;
        }
    }
}

// ---------------------------------------------------------------------------
// Kernel 2: 3x3 SAME conv for distinct (batch, expert) pairs, broadcast-write
// Grid: (1, COUT/CO_TILE, BATCH*NE).  Block: 256 threads.
// Each thread owns 4 pixels (tid, tid+256, tid+512, tid+768) x 8 out-channels.
// ---------------------------------------------------------------------------
__global__ __launch_bounds__(256, 2)
void conv_kernel(const float* __restrict__ x,
                 const float* __restrict__ we,
                 const float* __restrict__ be,
                 float* __restrict__ out) {
    const int z   = blockIdx.z;
    const int i   = z & (BATCH - 1);   // input batch
    const int e   = z >> 4;            // expert
    const int co0 = blockIdx.y * CO_TILE;
    const int tid = threadIdx.x;

    __shared__ int   sDec[BATCH];
    __shared__ float sX[CI_CHUNK][HALO * HALO];
    __shared__ float sW[CO_TILE * CI_CHUNK * 9];

    if (tid < BATCH) sDec[tid] = g_decisions[tid];
    __syncthreads();

    bool need = false;
    #pragma unroll
    for (int j = 0; j < BATCH; j++) need |= (sDec[j] == e);
    if (!need) return;   // block-uniform exit: skip unused experts entirely

    float acc[CO_TILE][4];
    #pragma unroll
    for (int co = 0; co < CO_TILE; co++)
        #pragma unroll
        for (int k = 0; k < 4; k++) acc[co][k] = 0.f;

    const float* xb = x  + (size_t)i * CIN * HW;
    const float* wb = we + ((size_t)e * COUT + co0) * (size_t)CIN * 9;

    int px[4], py[4];
    #pragma unroll
    for (int k = 0; k < 4; k++) {
        int p = tid + k * 256;
        py[k] = p >> 5;
        px[k] = p & 31;
    }

    for (int c0 = 0; c0 < CIN; c0 += CI_CHUNK) {
        __syncthreads();  // protect smem reuse from previous iteration

        // --- cooperative load of X chunk with 1-pixel zero halo ---
        for (int idx = tid; idx < CI_CHUNK * HALO * HALO; idx += 256) {
            int c   = idx / (HALO * HALO);
            int rem = idx - c * (HALO * HALO);
            int r   = rem / HALO;
            int col = rem - r * HALO;
            int gy  = r - 1, gx = col - 1;
            float v = 0.f;
            if ((unsigned)gy < 32u && (unsigned)gx < 32u)
                v = xb[(size_t)(c0 + c) * HW + gy * WW + gx];
            sX[c][rem] = v;
        }
        // --- cooperative load of weights: 8 co x 8 ci x 9 taps ---
        for (int idx = tid; idx < CO_TILE * CI_CHUNK * 9; idx += 256) {
            int co  = idx / (CI_CHUNK * 9);
            int rem = idx - co * (CI_CHUNK * 9);
            sW[idx] = wb[(size_t)co * CIN * 9 + (size_t)c0 * 9 + rem];
        }
        __syncthreads();

        #pragma unroll 1
        for (int c = 0; c < CI_CHUNK; c++) {
            // load 4 pixel neighborhoods (36 regs), reused across 8 co
            float xv[4][9];
            #pragma unroll
            for (int k = 0; k < 4; k++) {
                #pragma unroll
                for (int t = 0; t < 9; t++)
                    xv[k][t] = sX[c][(py[k] + t / 3) * HALO + px[k] + (t % 3)];
            }
            #pragma unroll
            for (int co = 0; co < CO_TILE; co++) {
                float wr[9];
                #pragma unroll
                for (int t = 0; t < 9; t++)
                    wr[t] = sW[(co * CI_CHUNK + c) * 9 + t];   // broadcast LDS
                #pragma unroll
                for (int k = 0; k < 4; k++)
                    #pragma unroll
                    for (int t = 0; t < 9; t++)
                        acc[co][k] = fmaf(xv[k][t], wr[t], acc[co][k]);
            }
        }
    }

    // --- epilogue: bias + relu, write every output block using this expert ---
    float bias[CO_TILE];
    #pragma unroll
    for (int co = 0; co < CO_TILE; co++) bias[co] = be[e * COUT + co0 + co];

    #pragma unroll 1
    for (int j = 0; j < BATCH; j++) {
        if (sDec[j] != e) continue;
        float* ob = out + ((size_t)(j * BATCH + i) * COUT + co0) * HW;
        #pragma unroll
        for (int co = 0; co < CO_TILE; co++) {
            #pragma unroll
            for (int k = 0; k < 4; k++) {
                float v = acc[co][k] + bias[co];
                ob[(size_t)co * HW + tid + k * 256] = fmaxf(v, 0.f);
            }
        }
    }
}

// ---------------------------------------------------------------------------
extern "C" void kernel_launch(void* const* d_in, const int* in_sizes, int n_in,
                              void* d_out, int out_size) {
    const float* x  = (const float*)d_in[0];
    const float* wc = (const float*)d_in[1];
    const float* bc = (const float*)d_in[2];
    const float* we = (const float*)d_in[3];
    const float* be = (const float*)d_in[4];
    float* out = (float*)d_out;

    router_kernel<<<BATCH, 256>>>(x, wc, bc);

    dim3 grid(1, COUT / CO_TILE, BATCH * NE);
    conv_kernel<<<grid, 256>>>(x, we, be, out);
}

// round 4
// speedup vs baseline: 4.4261x; 4.4261x over previous
#include <cuda_runtime.h>
#include <cuda_fp16.h>
#include <stdint.h>

#define BATCH 16
#define CIN   256
#define COUT  256
#define HW    1024
#define NE    8
#define KTOT  2304          /* 9 taps * 256 ci, tap-major: k = t*256+ci */
#define NCHUNK 72           /* 2 terms * 36 chunks of 64 halves */
#define STAGE 49152         /* A 16KB + B 32KB */

// ---------------- helpers ----------------
__device__ __forceinline__ uint32_t smem_u32(const void* p) {
    uint32_t a;
    asm("{ .reg .u64 t; cvta.to.shared.u64 t, %1; cvt.u32.u64 %0, t; }" : "=r"(a) : "l"(p));
    return a;
}
#define SWZ(off) ((off) ^ (((off) >> 3) & 0x70))

#define LDSM_X4(r, addr) \
    asm volatile("ldmatrix.sync.aligned.m8n8.x4.shared.b16 {%0,%1,%2,%3}, [%4];" \
        : "=r"((r)[0]), "=r"((r)[1]), "=r"((r)[2]), "=r"((r)[3]) : "r"(addr))

#define MMA16816(d, a, b0, b1) \
    asm volatile("mma.sync.aligned.m16n8k16.row.col.f32.f16.f16.f32 " \
        "{%0,%1,%2,%3}, {%4,%5,%6,%7}, {%8,%9}, {%0,%1,%2,%3};" \
        : "+f"((d)[0]), "+f"((d)[1]), "+f"((d)[2]), "+f"((d)[3]) \
        : "r"((a)[0]), "r"((a)[1]), "r"((a)[2]), "r"((a)[3]), "r"(b0), "r"(b1))

// ---------------- device scratch ----------------
__device__ int g_decisions[BATCH];
__device__ __align__(256) __half g_xh[(size_t)BATCH * HW * KTOT];   // 75.5 MB
__device__ __align__(256) __half g_xl[(size_t)BATCH * HW * KTOT];   // 75.5 MB
__device__ __align__(256) __half g_wh[(size_t)NE * COUT * KTOT];    // 9.4 MB

__device__ __forceinline__ uint32_t pack2(float v0, float v1) {
    __half h0 = __float2half_rn(v0), h1 = __float2half_rn(v1);
    return ((uint32_t)__half_as_ushort(h1) << 16) | __half_as_ushort(h0);
}

// ---------------- kernel 1: router ----------------
__global__ void router_kernel(const float* __restrict__ x,
                              const float* __restrict__ wc,
                              const float* __restrict__ bc) {
    int b = blockIdx.x, tid = threadIdx.x, warp = tid >> 5, lane = tid & 31;
    __shared__ float sPooled[CIN];
    __shared__ float sLog[NE];
    const float* xb = x + (size_t)b * CIN * HW;
    for (int ci = warp; ci < CIN; ci += 8) {
        const float* p = xb + (size_t)ci * HW;
        float s = 0.f;
        #pragma unroll 4
        for (int k = lane; k < HW; k += 32) s += p[k];
        #pragma unroll
        for (int o = 16; o > 0; o >>= 1) s += __shfl_xor_sync(0xffffffffu, s, o);
        if (lane == 0) sPooled[ci] = s * (1.0f / HW);
    }
    __syncthreads();
    if (warp == 0) {
        if (lane < NE) {
            const float* w = wc + lane * CIN;
            float s = 0.f;
            #pragma unroll 8
            for (int k = 0; k < CIN; k++) s += sPooled[k] * w[k];
            sLog[lane] = s + bc[lane];
        }
        __syncwarp();
        if (lane == 0) {
            float best = sLog[0]; int bi = 0;
            #pragma unroll
            for (int e = 1; e < NE; e++) if (sLog[e] > best) { best = sLog[e]; bi = e; }
            g_decisions[b] = bi;
        }
    }
}

// ---------------- kernel 2: weight reorder to fp16, tap-major ----------------
__global__ void wprep_kernel(const float* __restrict__ we) {
    __shared__ float sW[KTOT];
    int row = blockIdx.x;                        // e*256+co
    const float* src = we + (size_t)row * KTOT;  // [ci][t] row-major
    for (int t = threadIdx.x; t < KTOT; t += 256) sW[t] = src[t];
    __syncthreads();
    uint32_t* dH = (uint32_t*)(g_wh + (size_t)row * KTOT);
    for (int o2 = threadIdx.x; o2 < KTOT / 2; o2 += 256) {
        int k0 = o2 * 2;
        int t0 = k0 >> 8, ci0 = k0 & 255;        // dst k = t*256+ci, ci0 even
        dH[o2] = pack2(sW[ci0 * 9 + t0], sW[(ci0 + 1) * 9 + t0]);
    }
}

// ---------------- kernel 3: im2col + fp16 hi/lo split ----------------
// grid (32 y, 16 i, 4 ci-quarter), block 256.  xcol[i][p][k], k = t*256+ci.
__global__ void im2col_kernel(const float* __restrict__ x) {
    __shared__ float sF[3 * 64 * 33];            // [r3][ci4][px], pitch 33
    int y = blockIdx.x, i = blockIdx.y, q = blockIdx.z;
    for (int idx = threadIdx.x; idx < 3 * 64 * 32; idx += 256) {
        int px = idx & 31, ci4 = (idx >> 5) & 63, r3 = idx >> 11;
        int r = y + r3 - 1;
        float v = 0.f;
        if ((unsigned)r < 32u)
            v = x[((size_t)i * CIN + q * 64 + ci4) * HW + r * 32 + px];
        sF[(r3 * 64 + ci4) * 33 + px] = v;
    }
    __syncthreads();
    size_t rowBase = ((size_t)i * HW + (size_t)y * 32) * KTOT;
    uint32_t* dH = (uint32_t*)(g_xh + rowBase);
    uint32_t* dL = (uint32_t*)(g_xl + rowBase);
    for (int idx = threadIdx.x; idx < 32 * 9 * 32; idx += 256) {
        int cp = idx & 31;                        // ci-pair within quarter
        int tq = idx >> 5;
        int t = tq % 9, px = tq / 9;
        int r3 = t / 3, dx = (t % 3) - 1;
        int sx = px + dx;
        float v0 = 0.f, v1 = 0.f;
        if ((unsigned)sx < 32u) {
            v0 = sF[(r3 * 64 + 2 * cp) * 33 + sx];
            v1 = sF[(r3 * 64 + 2 * cp + 1) * 33 + sx];
        }
        __half h0 = __float2half_rn(v0), h1 = __float2half_rn(v1);
        float l0 = v0 - __half2float(h0), l1 = v1 - __half2float(h1);
        size_t o = (size_t)px * (KTOT / 2) + t * 128 + q * 32 + cp;
        dH[o] = ((uint32_t)__half_as_ushort(h1) << 16) | __half_as_ushort(h0);
        dL[o] = pack2(l0, l1);
    }
}

// ---------------- kernel 4: HMMA implicit GEMM ----------------
// D[co][pix] = Wh[co][K] * (Xh+Xl)[pix][K]^T.
// grid (4 pix-tiles of 256, 2 co-tiles of 128, 128 pairs), 256 threads.
// Warp tile 64co x 64pix (wm = wid&1, wn = wid>>1). acc frag rows=co, cols=pix.
__global__ void __launch_bounds__(256, 1)
gemm_kernel(const float* __restrict__ be, float* __restrict__ out) {
    extern __shared__ __align__(16) char dynraw[];
    char* dyn = (char*)(((uintptr_t)dynraw + 1023) & ~(uintptr_t)1023);
    const uint32_t dynu = smem_u32(dyn);

    __shared__ int sDec[BATCH];
    const int tid = threadIdx.x;
    const int ntile = blockIdx.x, mtile = blockIdx.y, pair = blockIdx.z;
    const int i = pair & 15, e = pair >> 4;

    if (tid < BATCH) sDec[tid] = g_decisions[tid];
    __syncthreads();
    bool need = false;
    #pragma unroll
    for (int j = 0; j < BATCH; j++) need |= (sDec[j] == e);
    if (!need) return;

    const int lane = tid & 31, wid = tid >> 5;
    const int wm = wid & 1, wn = wid >> 1;

    // gmem load mapping: octet of lanes covers one 128B row-chunk
    const int ldRow = tid >> 3;                  // 0..31
    const int ldCol = (tid & 7) * 8;             // halves
    const __half* aBase = g_wh + (size_t)((e << 8) + (mtile << 7) + ldRow) * KTOT + ldCol;
    const size_t bRowOff = (size_t)((i << 10) + (ntile << 8) + ldRow) * KTOT + ldCol;
    const uint32_t stsOff = SWZ(ldRow * 128 + (tid & 7) * 16);

    float acc[4][8][4];
    #pragma unroll
    for (int ma = 0; ma < 4; ma++)
        #pragma unroll
        for (int na = 0; na < 8; na++)
            #pragma unroll
            for (int c = 0; c < 4; c++) acc[ma][na][c] = 0.f;

    // fragment smem offsets (within A / B regions)
    const uint32_t aFragBase = (uint32_t)((wm * 64 + (lane & 15)) * 128 + ((lane >> 4) << 4));
    const uint32_t bFragBase = (uint32_t)((wn * 64 + (lane & 7) + ((lane >> 4) << 3)) * 128
                                          + (((lane >> 3) & 1) << 4));

    uint4 ra[4], rb[8];
    {   // prefetch chunk 0 (term 0 = Xh, k0 = 0)
        #pragma unroll
        for (int jj = 0; jj < 4; jj++)
            ra[jj] = *(const uint4*)(aBase + (size_t)jj * 32 * KTOT);
        #pragma unroll
        for (int jj = 0; jj < 8; jj++)
            rb[jj] = *(const uint4*)(g_xh + bRowOff + (size_t)jj * 32 * KTOT);
    }

    for (int it = 0; it < NCHUNK; ++it) {
        const uint32_t bufo = (it & 1) ? STAGE : 0;
        char* st = dyn + bufo;
        #pragma unroll
        for (int jj = 0; jj < 4; jj++)
            *(uint4*)(st + (stsOff + jj * 32 * 128)) = ra[jj];
        #pragma unroll
        for (int jj = 0; jj < 8; jj++)
            *(uint4*)(st + 16384 + (stsOff + jj * 32 * 128)) = rb[jj];
        __syncthreads();

        if (it < NCHUNK - 1) {
            const int nit = it + 1;
            const int term = nit >= 36;
            const int k0 = (term ? nit - 36 : nit) << 6;
            #pragma unroll
            for (int jj = 0; jj < 4; jj++)
                ra[jj] = *(const uint4*)(aBase + k0 + (size_t)jj * 32 * KTOT);
            const __half* Bg = term ? g_xl : g_xh;
            #pragma unroll
            for (int jj = 0; jj < 8; jj++)
                rb[jj] = *(const uint4*)(Bg + bRowOff + k0 + (size_t)jj * 32 * KTOT);
        }

        const uint32_t bA = dynu + bufo;
        const uint32_t bB = bA + 16384;
        #pragma unroll
        for (int s = 0; s < 4; s++) {
            uint32_t af[4][4], bf[4][4];
            #pragma unroll
            for (int ma = 0; ma < 4; ma++)
                LDSM_X4(af[ma], bA + SWZ(aFragBase + ma * 2048 + s * 32));
            #pragma unroll
            for (int nb = 0; nb < 4; nb++)
                LDSM_X4(bf[nb], bB + SWZ(bFragBase + nb * 2048 + s * 32));
            #pragma unroll
            for (int ma = 0; ma < 4; ma++)
                #pragma unroll
                for (int na = 0; na < 8; na++)
                    MMA16816(acc[ma][na], af[ma], bf[na >> 1][(na & 1) * 2],
                             bf[na >> 1][(na & 1) * 2 + 1]);
        }
        __syncthreads();
    }

    // ---------------- epilogue: bias + relu, broadcast to matching j ----------
    const int coBase = (mtile << 7) + wm * 64 + (lane >> 2);
    const int pixBase = (ntile << 8) + wn * 64 + 2 * (lane & 3);
    float bias0[4], bias1[4];
    #pragma unroll
    for (int ma = 0; ma < 4; ma++) {
        bias0[ma] = be[(e << 8) + coBase + ma * 16];
        bias1[ma] = be[(e << 8) + coBase + ma * 16 + 8];
    }
    #pragma unroll 1
    for (int j = 0; j < BATCH; j++) {
        if (sDec[j] != e) continue;
        float* ob = out + ((size_t)(j * BATCH + i) << 18);   // *256*1024
        #pragma unroll
        for (int ma = 0; ma < 4; ma++) {
            const int co = coBase + ma * 16;
            #pragma unroll
            for (int na = 0; na < 8; na++) {
                const int pix = pixBase + na * 8;
                float2 v0, v1;
                v0.x = fmaxf(acc[ma][na][0] + bias0[ma], 0.f);
                v0.y = fmaxf(acc[ma][na][1] + bias0[ma], 0.f);
                v1.x = fmaxf(acc[ma][na][2] + bias1[ma], 0.f);
                v1.y = fmaxf(acc[ma][na][3] + bias1[ma], 0.f);
                *(float2*)(ob + (size_t)co * HW + pix)       = v0;
                *(float2*)(ob + (size_t)(co + 8) * HW + pix) = v1;
            }
        }
    }
}

// ---------------------------------------------------------------------------
extern "C" void kernel_launch(void* const* d_in, const int* in_sizes, int n_in,
                              void* d_out, int out_size) {
    const float* x  = (const float*)d_in[0];
    const float* wc = (const float*)d_in[1];
    const float* bc = (const float*)d_in[2];
    const float* we = (const float*)d_in[3];
    const float* be = (const float*)d_in[4];
    float* out = (float*)d_out;

    static int smemSet = 0;
    if (!smemSet) {
        cudaFuncSetAttribute(gemm_kernel, cudaFuncAttributeMaxDynamicSharedMemorySize,
                             2 * STAGE + 1024);
        smemSet = 1;
    }

    router_kernel<<<BATCH, 256>>>(x, wc, bc);
    wprep_kernel<<<NE * COUT, 256>>>(we);
    im2col_kernel<<<dim3(32, BATCH, 4), 256>>>(x);
    gemm_kernel<<<dim3(4, 2, BATCH * NE), 256, 2 * STAGE + 1024>>>(be, out);
}

// round 5
// speedup vs baseline: 7.9042x; 1.7858x over previous
#include <cuda_runtime.h>
#include <cuda_fp16.h>
#include <stdint.h>

#define BATCH 16
#define CIN   256
#define COUT  256
#define HW    1024
#define NE    8
#define KTOT  2304          /* 9 taps * 256 ci, tap-major: k = t*256+ci */
#define NCHUNK 36           /* 36 k-chunks of 64 halves */
#define STAGE 49152         /* A 16KB + B 32KB */
#define NSTAGE 4

// ---------------- helpers ----------------
__device__ __forceinline__ uint32_t smem_u32(const void* p) {
    uint32_t a;
    asm("{ .reg .u64 t; cvta.to.shared.u64 t, %1; cvt.u32.u64 %0, t; }" : "=r"(a) : "l"(p));
    return a;
}
#define SWZ(off) ((off) ^ (((off) >> 3) & 0x70))

#define CP_ASYNC16(dst, src) \
    asm volatile("cp.async.cg.shared.global [%0], [%1], 16;" :: "r"(dst), "l"(src) : "memory")
#define CP_COMMIT() asm volatile("cp.async.commit_group;" ::: "memory")
#define CP_WAIT2()  asm volatile("cp.async.wait_group 2;" ::: "memory")

#define LDSM_X4(r, addr) \
    asm volatile("ldmatrix.sync.aligned.m8n8.x4.shared.b16 {%0,%1,%2,%3}, [%4];" \
        : "=r"((r)[0]), "=r"((r)[1]), "=r"((r)[2]), "=r"((r)[3]) : "r"(addr))

#define MMA16816(d, a, b0, b1) \
    asm volatile("mma.sync.aligned.m16n8k16.row.col.f32.f16.f16.f32 " \
        "{%0,%1,%2,%3}, {%4,%5,%6,%7}, {%8,%9}, {%0,%1,%2,%3};" \
        : "+f"((d)[0]), "+f"((d)[1]), "+f"((d)[2]), "+f"((d)[3]) \
        : "r"((a)[0]), "r"((a)[1]), "r"((a)[2]), "r"((a)[3]), "r"(b0), "r"(b1))

// ---------------- device scratch ----------------
__device__ int g_decisions[BATCH];
__device__ __align__(256) __half g_xh[(size_t)BATCH * HW * KTOT];   // 75.5 MB
__device__ __align__(256) __half g_wh[(size_t)NE * COUT * KTOT];    // 9.4 MB

__device__ __forceinline__ uint32_t pack2(float v0, float v1) {
    __half h0 = __float2half_rn(v0), h1 = __float2half_rn(v1);
    return ((uint32_t)__half_as_ushort(h1) << 16) | __half_as_ushort(h0);
}

// ---------------- kernel 1: router ----------------
__global__ void router_kernel(const float* __restrict__ x,
                              const float* __restrict__ wc,
                              const float* __restrict__ bc) {
    int b = blockIdx.x, tid = threadIdx.x, warp = tid >> 5, lane = tid & 31;
    __shared__ float sPooled[CIN];
    __shared__ float sLog[NE];
    const float* xb = x + (size_t)b * CIN * HW;
    for (int ci = warp; ci < CIN; ci += 8) {
        const float* p = xb + (size_t)ci * HW;
        float s = 0.f;
        #pragma unroll 4
        for (int k = lane; k < HW; k += 32) s += p[k];
        #pragma unroll
        for (int o = 16; o > 0; o >>= 1) s += __shfl_xor_sync(0xffffffffu, s, o);
        if (lane == 0) sPooled[ci] = s * (1.0f / HW);
    }
    __syncthreads();
    if (warp == 0) {
        if (lane < NE) {
            const float* w = wc + lane * CIN;
            float s = 0.f;
            #pragma unroll 8
            for (int k = 0; k < CIN; k++) s += sPooled[k] * w[k];
            sLog[lane] = s + bc[lane];
        }
        __syncwarp();
        if (lane == 0) {
            float best = sLog[0]; int bi = 0;
            #pragma unroll
            for (int e = 1; e < NE; e++) if (sLog[e] > best) { best = sLog[e]; bi = e; }
            g_decisions[b] = bi;
        }
    }
}

// ---------------- kernel 2: weight reorder to fp16, tap-major ----------------
__global__ void wprep_kernel(const float* __restrict__ we) {
    __shared__ float sW[KTOT];
    int row = blockIdx.x;                        // e*256+co
    const float* src = we + (size_t)row * KTOT;  // [ci][t] row-major
    for (int t = threadIdx.x; t < KTOT; t += 256) sW[t] = src[t];
    __syncthreads();
    uint32_t* dH = (uint32_t*)(g_wh + (size_t)row * KTOT);
    for (int o2 = threadIdx.x; o2 < KTOT / 2; o2 += 256) {
        int k0 = o2 * 2;
        int t0 = k0 >> 8, ci0 = k0 & 255;        // dst k = t*256+ci, ci0 even
        dH[o2] = pack2(sW[ci0 * 9 + t0], sW[(ci0 + 1) * 9 + t0]);
    }
}

// ---------------- kernel 3: im2col fp16 ----------------
// grid (32 y, 16 i, 4 ci-quarter), block 256.  xcol[i][p][k], k = t*256+ci.
__global__ void im2col_kernel(const float* __restrict__ x) {
    __shared__ float sF[3 * 64 * 33];            // [r3][ci4][px], pitch 33
    int y = blockIdx.x, i = blockIdx.y, q = blockIdx.z;
    for (int idx = threadIdx.x; idx < 3 * 64 * 32; idx += 256) {
        int px = idx & 31, ci4 = (idx >> 5) & 63, r3 = idx >> 11;
        int r = y + r3 - 1;
        float v = 0.f;
        if ((unsigned)r < 32u)
            v = x[((size_t)i * CIN + q * 64 + ci4) * HW + r * 32 + px];
        sF[(r3 * 64 + ci4) * 33 + px] = v;
    }
    __syncthreads();
    size_t rowBase = ((size_t)i * HW + (size_t)y * 32) * KTOT;
    uint32_t* dH = (uint32_t*)(g_xh + rowBase);
    for (int idx = threadIdx.x; idx < 32 * 9 * 32; idx += 256) {
        int cp = idx & 31;                        // ci-pair within quarter
        int tq = idx >> 5;
        int t = tq % 9, px = tq / 9;
        int r3 = t / 3, dx = (t % 3) - 1;
        int sx = px + dx;
        float v0 = 0.f, v1 = 0.f;
        if ((unsigned)sx < 32u) {
            v0 = sF[(r3 * 64 + 2 * cp) * 33 + sx];
            v1 = sF[(r3 * 64 + 2 * cp + 1) * 33 + sx];
        }
        size_t o = (size_t)px * (KTOT / 2) + t * 128 + q * 32 + cp;
        dH[o] = pack2(v0, v1);
    }
}

// ---------------- kernel 4: HMMA implicit GEMM, cp.async 4-stage ----------------
// D[co][pix] = Wh[co][K] * Xh[pix][K]^T.
// grid (4 pix-tiles of 256, 2 co-tiles of 128, 128 pairs), 256 threads.
__global__ void __launch_bounds__(256, 1)
gemm_kernel(const float* __restrict__ be, float* __restrict__ out) {
    extern __shared__ __align__(16) char dynraw[];
    char* dyn = (char*)(((uintptr_t)dynraw + 1023) & ~(uintptr_t)1023);
    const uint32_t dynu = smem_u32(dyn);

    __shared__ int sDec[BATCH];
    const int tid = threadIdx.x;
    const int ntile = blockIdx.x, mtile = blockIdx.y, pair = blockIdx.z;
    const int i = pair & 15, e = pair >> 4;

    if (tid < BATCH) sDec[tid] = g_decisions[tid];
    __syncthreads();
    bool need = false;
    #pragma unroll
    for (int j = 0; j < BATCH; j++) need |= (sDec[j] == e);
    if (!need) return;

    const int lane = tid & 31, wid = tid >> 5;
    const int wm = wid & 1, wn = wid >> 1;

    // gmem->smem mapping: lane octet covers one 128B k-row chunk
    const int ldRow = tid >> 3;                  // 0..31
    const __half* aBase = g_wh + (size_t)((e << 8) + (mtile << 7) + ldRow) * KTOT + (tid & 7) * 8;
    const __half* bBase = g_xh + (size_t)((i << 10) + (ntile << 8) + ldRow) * KTOT + (tid & 7) * 8;
    const uint32_t stsOff = SWZ(ldRow * 128 + (tid & 7) * 16);

    float acc[4][8][4];
    #pragma unroll
    for (int ma = 0; ma < 4; ma++)
        #pragma unroll
        for (int na = 0; na < 8; na++)
            #pragma unroll
            for (int c = 0; c < 4; c++) acc[ma][na][c] = 0.f;

    const uint32_t aFragBase = (uint32_t)((wm * 64 + (lane & 15)) * 128 + ((lane >> 4) << 4));
    const uint32_t bFragBase = (uint32_t)((wn * 64 + (lane & 7) + ((lane >> 4) << 3)) * 128
                                          + (((lane >> 3) & 1) << 4));

    // stage loader: chunk ck into stage s
    auto load_stage = [&](int s, int ck) {
        const uint32_t st = dynu + s * STAGE;
        const int k0 = ck << 6;
        #pragma unroll
        for (int jj = 0; jj < 4; jj++)
            CP_ASYNC16(st + stsOff + jj * 32 * 128,
                       (const char*)(aBase + k0 + (size_t)jj * 32 * KTOT));
        #pragma unroll
        for (int jj = 0; jj < 8; jj++)
            CP_ASYNC16(st + 16384 + stsOff + jj * 32 * 128,
                       (const char*)(bBase + k0 + (size_t)jj * 32 * KTOT));
    };

    #pragma unroll
    for (int s = 0; s < NSTAGE - 1; s++) { load_stage(s, s); CP_COMMIT(); }

    for (int it = 0; it < NCHUNK; ++it) {
        CP_WAIT2();
        __syncthreads();

        const int pf = it + NSTAGE - 1;
        if (pf < NCHUNK) load_stage(pf & (NSTAGE - 1), pf);
        CP_COMMIT();

        const uint32_t bA = dynu + (it & (NSTAGE - 1)) * STAGE;
        const uint32_t bB = bA + 16384;
        #pragma unroll
        for (int s = 0; s < 4; s++) {
            uint32_t af[4][4], bf[4][4];
            #pragma unroll
            for (int ma = 0; ma < 4; ma++)
                LDSM_X4(af[ma], bA + SWZ(aFragBase + ma * 2048 + s * 32));
            #pragma unroll
            for (int nb = 0; nb < 4; nb++)
                LDSM_X4(bf[nb], bB + SWZ(bFragBase + nb * 2048 + s * 32));
            #pragma unroll
            for (int ma = 0; ma < 4; ma++)
                #pragma unroll
                for (int na = 0; na < 8; na++)
                    MMA16816(acc[ma][na], af[ma], bf[na >> 1][(na & 1) * 2],
                             bf[na >> 1][(na & 1) * 2 + 1]);
        }
    }

    // ---------------- epilogue: bias + relu, broadcast to matching j ----------
    const int coBase = (mtile << 7) + wm * 64 + (lane >> 2);
    const int pixBase = (ntile << 8) + wn * 64 + 2 * (lane & 3);
    float bias0[4], bias1[4];
    #pragma unroll
    for (int ma = 0; ma < 4; ma++) {
        bias0[ma] = be[(e << 8) + coBase + ma * 16];
        bias1[ma] = be[(e << 8) + coBase + ma * 16 + 8];
    }
    #pragma unroll 1
    for (int j = 0; j < BATCH; j++) {
        if (sDec[j] != e) continue;
        float* ob = out + ((size_t)(j * BATCH + i) << 18);   // *256*1024
        #pragma unroll
        for (int ma = 0; ma < 4; ma++) {
            const int co = coBase + ma * 16;
            #pragma unroll
            for (int na = 0; na < 8; na++) {
                const int pix = pixBase + na * 8;
                float2 v0, v1;
                v0.x = fmaxf(acc[ma][na][0] + bias0[ma], 0.f);
                v0.y = fmaxf(acc[ma][na][1] + bias0[ma], 0.f);
                v1.x = fmaxf(acc[ma][na][2] + bias1[ma], 0.f);
                v1.y = fmaxf(acc[ma][na][3] + bias1[ma], 0.f);
                *(float2*)(ob + (size_t)co * HW + pix)       = v0;
                *(float2*)(ob + (size_t)(co + 8) * HW + pix) = v1;
            }
        }
    }
}

// ---------------------------------------------------------------------------
extern "C" void kernel_launch(void* const* d_in, const int* in_sizes, int n_in,
                              void* d_out, int out_size) {
    const float* x  = (const float*)d_in[0];
    const float* wc = (const float*)d_in[1];
    const float* bc = (const float*)d_in[2];
    const float* we = (const float*)d_in[3];
    const float* be = (const float*)d_in[4];
    float* out = (float*)d_out;

    static int smemSet = 0;
    if (!smemSet) {
        cudaFuncSetAttribute(gemm_kernel, cudaFuncAttributeMaxDynamicSharedMemorySize,
                             NSTAGE * STAGE + 1024);
        smemSet = 1;
    }

    router_kernel<<<BATCH, 256>>>(x, wc, bc);
    wprep_kernel<<<NE * COUT, 256>>>(we);
    im2col_kernel<<<dim3(32, BATCH, 4), 256>>>(x);
    gemm_kernel<<<dim3(4, 2, BATCH * NE), 256, NSTAGE * STAGE + 1024>>>(be, out);
}

// round 6
// speedup vs baseline: 8.3537x; 1.0569x over previous
#include <cuda_runtime.h>
#include <cuda_fp16.h>
#include <stdint.h>

#define BATCH 16
#define CIN   256
#define COUT  256
#define HW    1024
#define NE    8
#define NCHUNK 18             /* 9 taps * 2 ci-halves of 128 */
#define STAGE  98304          /* A 2x16KB + B 2x32KB */
#define SMEM_TOTAL (2 * STAGE + 1024)

// ---------------- helpers ----------------
__device__ __forceinline__ uint32_t smem_u32(const void* p) {
    uint32_t a;
    asm("{ .reg .u64 t; cvta.to.shared.u64 t, %1; cvt.u32.u64 %0, t; }" : "=r"(a) : "l"(p));
    return a;
}
#define SWZ(off) ((off) ^ (((off) >> 3) & 0x70))

#define CP_ASYNC16(dst, src) \
    asm volatile("cp.async.cg.shared.global [%0], [%1], 16;" :: "r"(dst), "l"(src) : "memory")
#define CP_COMMIT() asm volatile("cp.async.commit_group;" ::: "memory")
#define CP_WAIT0()  asm volatile("cp.async.wait_group 0;" ::: "memory")

#define LDSM_X4(r, addr) \
    asm volatile("ldmatrix.sync.aligned.m8n8.x4.shared.b16 {%0,%1,%2,%3}, [%4];" \
        : "=r"((r)[0]), "=r"((r)[1]), "=r"((r)[2]), "=r"((r)[3]) : "r"(addr))
#define LDSM_X4T(r, addr) \
    asm volatile("ldmatrix.sync.aligned.m8n8.x4.trans.shared.b16 {%0,%1,%2,%3}, [%4];" \
        : "=r"((r)[0]), "=r"((r)[1]), "=r"((r)[2]), "=r"((r)[3]) : "r"(addr))

#define MMA16816(d, a, b0, b1) \
    asm volatile("mma.sync.aligned.m16n8k16.row.col.f32.f16.f16.f32 " \
        "{%0,%1,%2,%3}, {%4,%5,%6,%7}, {%8,%9}, {%0,%1,%2,%3};" \
        : "+f"((d)[0]), "+f"((d)[1]), "+f"((d)[2]), "+f"((d)[3]) \
        : "r"((a)[0]), "r"((a)[1]), "r"((a)[2]), "r"((a)[3]), "r"(b0), "r"(b1))

// ---------------- device scratch ----------------
__device__ int g_decisions[BATCH];
// weights, tap-major fp16 pairs: [e][t][co][ci/2] u32
__device__ __align__(256) uint32_t g_wh[(size_t)NE * 9 * COUT * 128];          // 9.4 MB
// padded+shifted X fp16 pairs: [i][dx 3][ci][34 rows][16 px-pairs] u32
__device__ __align__(256) uint32_t g_xp[(size_t)BATCH * 3 * CIN * 34 * 16];    // 26.7 MB

__device__ __forceinline__ uint32_t pack2(float v0, float v1) {
    __half h0 = __float2half_rn(v0), h1 = __float2half_rn(v1);
    return ((uint32_t)__half_as_ushort(h1) << 16) | __half_as_ushort(h0);
}

// ---------------- kernel 1: router ----------------
__global__ void router_kernel(const float* __restrict__ x,
                              const float* __restrict__ wc,
                              const float* __restrict__ bc) {
    int b = blockIdx.x, tid = threadIdx.x, warp = tid >> 5, lane = tid & 31;
    __shared__ float sPooled[CIN];
    __shared__ float sLog[NE];
    const float* xb = x + (size_t)b * CIN * HW;
    for (int ci = warp; ci < CIN; ci += 8) {
        const float* p = xb + (size_t)ci * HW;
        float s = 0.f;
        #pragma unroll 4
        for (int k = lane; k < HW; k += 32) s += p[k];
        #pragma unroll
        for (int o = 16; o > 0; o >>= 1) s += __shfl_xor_sync(0xffffffffu, s, o);
        if (lane == 0) sPooled[ci] = s * (1.0f / HW);
    }
    __syncthreads();
    if (warp == 0) {
        if (lane < NE) {
            const float* w = wc + lane * CIN;
            float s = 0.f;
            #pragma unroll 8
            for (int k = 0; k < CIN; k++) s += sPooled[k] * w[k];
            sLog[lane] = s + bc[lane];
        }
        __syncwarp();
        if (lane == 0) {
            float best = sLog[0]; int bi = 0;
            #pragma unroll
            for (int e = 1; e < NE; e++) if (sLog[e] > best) { best = sLog[e]; bi = e; }
            g_decisions[b] = bi;
        }
    }
}

// ---------------- kernel 2: fused prep (xpad + weight reorder) ----------------
// blocks [0,4096): xpad for (i = b>>8, ci = b&255)
// blocks [4096,6144): weight row (e*256+co) -> [e][t][co][ci]
__global__ void prep_kernel(const float* __restrict__ x, const float* __restrict__ we) {
    __shared__ float s[2304];
    const int b = blockIdx.x, tid = threadIdx.x;
    if (b < 4096) {
        const int i = b >> 8, ci = b & 255;
        const float* src = x + ((size_t)i * CIN + ci) * HW;
        for (int k = tid; k < 1024; k += 256) s[k] = src[k];
        __syncthreads();
        uint32_t* dst = g_xp + (((size_t)i * 3 * CIN + ci) * 34) * 16;  // + dxs*CIN*34*16
        for (int idx = tid; idx < 3 * 34 * 16; idx += 256) {
            int xp = (idx & 15) * 2;
            int rest = idx >> 4;
            int yy = rest % 34;
            int dxs = rest / 34;
            float v0 = 0.f, v1 = 0.f;
            if (yy >= 1 && yy <= 32) {
                int sx0 = xp + dxs - 1;
                if ((unsigned)sx0 < 32u)       v0 = s[(yy - 1) * 32 + sx0];
                if ((unsigned)(sx0 + 1) < 32u) v1 = s[(yy - 1) * 32 + sx0 + 1];
            }
            dst[((size_t)dxs * CIN * 34 + yy) * 16 + (idx & 15)] = pack2(v0, v1);
        }
    } else {
        const int row = b - 4096;                 // e*256+co
        const int e = row >> 8, co = row & 255;
        const float* src = we + (size_t)row * 2304;  // [ci][3][3]
        for (int k = tid; k < 2304; k += 256) s[k] = src[k];
        __syncthreads();
        for (int idx = tid; idx < 9 * 128; idx += 256) {
            int t = idx >> 7, cip = idx & 127;
            int ci0 = cip * 2;
            g_wh[((size_t)(e * 9 + t) * COUT + co) * 128 + cip] =
                pack2(s[ci0 * 9 + t], s[(ci0 + 1) * 9 + t]);
        }
    }
}

// ---------------- kernel 3: HMMA implicit GEMM (no im2col tensor) ----------------
// D[co][pix] = sum_t W_t[co][ci] * Xshift_t[ci][pix]
// grid (4 px-tiles of 256, 2 co-tiles of 128, 128 pairs), 256 threads.
__global__ void __launch_bounds__(256, 1)
gemm_kernel(const float* __restrict__ be, float* __restrict__ out) {
    extern __shared__ __align__(16) char dynraw[];
    char* dyn = (char*)(((uintptr_t)dynraw + 1023) & ~(uintptr_t)1023);
    const uint32_t dynu = smem_u32(dyn);

    __shared__ int sDec[BATCH];
    const int tid = threadIdx.x;
    const int ntile = blockIdx.x, mtile = blockIdx.y, pair = blockIdx.z;
    const int i = pair & 15, e = pair >> 4;

    if (tid < BATCH) sDec[tid] = g_decisions[tid];
    __syncthreads();
    bool need = false;
    #pragma unroll
    for (int j = 0; j < BATCH; j++) need |= (sDec[j] == e);
    if (!need) return;

    const int lane = tid & 31, wid = tid >> 5;
    const int wm = wid & 1, wn = wid >> 1;
    const int y0 = ntile << 3;                    // first image row of px tile

    // A gmem->smem mapping (per 16KB half: 128 co rows x 128B)
    const int ldRow = tid >> 3, ldc = tid & 7;
    const uint32_t stsOffA = SWZ(ldRow * 128 + ldc * 16);

    float acc[4][8][4];
    #pragma unroll
    for (int ma = 0; ma < 4; ma++)
        #pragma unroll
        for (int na = 0; na < 8; na++)
            #pragma unroll
            for (int c = 0; c < 4; c++) acc[ma][na][c] = 0.f;

    // fragment address constants
    const uint32_t aFragBase = (uint32_t)((wm * 64 + (lane & 15)) * 128 + ((lane >> 4) << 4));
    const uint32_t bRowBase = (uint32_t)((lane & 15) * 512);
    uint32_t bConst[4];
    #pragma unroll
    for (int pb = 0; pb < 4; pb++)
        bConst[pb] = (uint32_t)((((wn << 6) + (pb << 4) + ((lane >> 4) << 3)) << 1)
                                ^ ((lane & 7) << 4));

    // stage loader: chunk it (t = it>>1, ci-half ch = it&1) into stage buf
    auto load_stage = [&](int buf, int it) {
        const int t = it >> 1, ch = it & 1;
        const int ty = t / 3, tx = t % 3;
        const uint32_t st = dynu + buf * STAGE;
        // A: [co 128][ci 128] as 2 halves of [co 128][64ci=128B]
        const uint32_t* wrow = g_wh + ((size_t)(e * 9 + t) * COUT + (mtile << 7) + ldRow) * 128
                               + (ch << 6) + ldc * 4;
        #pragma unroll
        for (int h = 0; h < 2; h++)
            #pragma unroll
            for (int jj = 0; jj < 4; jj++)
                CP_ASYNC16(st + h * 16384 + stsOffA + jj * 32 * 128,
                           (const char*)(wrow + h * 32 + jj * 32 * 128));
        // B: [ci 128][px 256] as 2 halves of [ci 64][512B]; per ci one contiguous 512B
        const size_t bRow64 = ((size_t)(i * 3 + tx) * CIN + (ch << 7)) * 34 + y0 + ty;  // 64B units
        #pragma unroll
        for (int h = 0; h < 2; h++) {
            #pragma unroll
            for (int jj = 0; jj < 8; jj++) {
                const int ciL = jj * 8 + wid;
                const uint32_t dst = st + 32768 + h * 32768 + ciL * 512
                                     + (((uint32_t)lane << 4) ^ ((uint32_t)wid << 4));
                const char* src = (const char*)g_xp
                                  + ((bRow64 + (size_t)(h * 64 + ciL) * 34) << 6) + lane * 16;
                CP_ASYNC16(dst, src);
            }
        }
    };

    load_stage(0, 0);
    CP_COMMIT();

    #pragma unroll 1
    for (int it = 0; it < NCHUNK; ++it) {
        CP_WAIT0();
        __syncthreads();
        if (it + 1 < NCHUNK) { load_stage((it + 1) & 1, it + 1); CP_COMMIT(); }

        const uint32_t bA = dynu + (it & 1) * STAGE;
        const uint32_t bB = bA + 32768;
        #pragma unroll
        for (int s = 0; s < 8; s++) {
            const uint32_t hA = bA + (s >> 2) * 16384;
            const uint32_t hB = bB + (s >> 2) * 32768 + ((s & 3) * 16) * 512 + bRowBase;
            uint32_t af[4][4], bf[4][4];
            #pragma unroll
            for (int ma = 0; ma < 4; ma++)
                LDSM_X4(af[ma], hA + SWZ(aFragBase + ma * 2048 + (s & 3) * 32));
            #pragma unroll
            for (int pb = 0; pb < 4; pb++)
                LDSM_X4T(bf[pb], hB + bConst[pb]);
            #pragma unroll
            for (int ma = 0; ma < 4; ma++)
                #pragma unroll
                for (int pb = 0; pb < 4; pb++) {
                    MMA16816(acc[ma][pb * 2],     af[ma], bf[pb][0], bf[pb][1]);
                    MMA16816(acc[ma][pb * 2 + 1], af[ma], bf[pb][2], bf[pb][3]);
                }
        }
    }

    // ---------------- epilogue: bias + relu, broadcast to matching j ----------
    const int coBase = (mtile << 7) + wm * 64 + (lane >> 2);
    const int pixBase = (ntile << 8) + wn * 64 + 2 * (lane & 3);
    float bias0[4], bias1[4];
    #pragma unroll
    for (int ma = 0; ma < 4; ma++) {
        bias0[ma] = be[(e << 8) + coBase + ma * 16];
        bias1[ma] = be[(e << 8) + coBase + ma * 16 + 8];
    }
    #pragma unroll 1
    for (int j = 0; j < BATCH; j++) {
        if (sDec[j] != e) continue;
        float* ob = out + ((size_t)(j * BATCH + i) << 18);   // *256*1024
        #pragma unroll
        for (int ma = 0; ma < 4; ma++) {
            const int co = coBase + ma * 16;
            #pragma unroll
            for (int na = 0; na < 8; na++) {
                const int pix = pixBase + na * 8;
                float2 v0, v1;
                v0.x = fmaxf(acc[ma][na][0] + bias0[ma], 0.f);
                v0.y = fmaxf(acc[ma][na][1] + bias0[ma], 0.f);
                v1.x = fmaxf(acc[ma][na][2] + bias1[ma], 0.f);
                v1.y = fmaxf(acc[ma][na][3] + bias1[ma], 0.f);
                *(float2*)(ob + (size_t)co * HW + pix)       = v0;
                *(float2*)(ob + (size_t)(co + 8) * HW + pix) = v1;
            }
        }
    }
}

// ---------------------------------------------------------------------------
extern "C" void kernel_launch(void* const* d_in, const int* in_sizes, int n_in,
                              void* d_out, int out_size) {
    const float* x  = (const float*)d_in[0];
    const float* wc = (const float*)d_in[1];
    const float* bc = (const float*)d_in[2];
    const float* we = (const float*)d_in[3];
    const float* be = (const float*)d_in[4];
    float* out = (float*)d_out;

    static int smemSet = 0;
    if (!smemSet) {
        cudaFuncSetAttribute(gemm_kernel, cudaFuncAttributeMaxDynamicSharedMemorySize,
                             SMEM_TOTAL);
        smemSet = 1;
    }

    router_kernel<<<BATCH, 256>>>(x, wc, bc);
    prep_kernel<<<4096 + NE * COUT, 256>>>(x, we);
    gemm_kernel<<<dim3(4, 2, BATCH * NE), 256, SMEM_TOTAL>>>(be, out);
}

// round 7
// speedup vs baseline: 10.4536x; 1.2514x over previous
#include <cuda_runtime.h>
#include <cuda_fp16.h>
#include <stdint.h>

#define BATCH 16
#define CIN   256
#define COUT  256
#define HW    1024
#define NE    8
#define NCHUNK 18             /* 9 taps * 2 ci-halves of 128 */
#define STAGE  98304          /* A 2x16KB + B 2x32KB */
#define SMEM_TOTAL (2 * STAGE + 1024)

// ---------------- helpers ----------------
__device__ __forceinline__ uint32_t smem_u32(const void* p) {
    uint32_t a;
    asm("{ .reg .u64 t; cvta.to.shared.u64 t, %1; cvt.u32.u64 %0, t; }" : "=r"(a) : "l"(p));
    return a;
}
#define SWZ(off) ((off) ^ (((off) >> 3) & 0x70))

#define CP_ASYNC16(dst, src) \
    asm volatile("cp.async.cg.shared.global [%0], [%1], 16;" :: "r"(dst), "l"(src) : "memory")
#define CP_COMMIT() asm volatile("cp.async.commit_group;" ::: "memory")
#define CP_WAIT0()  asm volatile("cp.async.wait_group 0;" ::: "memory")

#define LDSM_X4(r, addr) \
    asm volatile("ldmatrix.sync.aligned.m8n8.x4.shared.b16 {%0,%1,%2,%3}, [%4];" \
        : "=r"((r)[0]), "=r"((r)[1]), "=r"((r)[2]), "=r"((r)[3]) : "r"(addr))
#define LDSM_X4T(r, addr) \
    asm volatile("ldmatrix.sync.aligned.m8n8.x4.trans.shared.b16 {%0,%1,%2,%3}, [%4];" \
        : "=r"((r)[0]), "=r"((r)[1]), "=r"((r)[2]), "=r"((r)[3]) : "r"(addr))

#define MMA16816(d, a, b0, b1) \
    asm volatile("mma.sync.aligned.m16n8k16.row.col.f32.f16.f16.f32 " \
        "{%0,%1,%2,%3}, {%4,%5,%6,%7}, {%8,%9}, {%0,%1,%2,%3};" \
        : "+f"((d)[0]), "+f"((d)[1]), "+f"((d)[2]), "+f"((d)[3]) \
        : "r"((a)[0]), "r"((a)[1]), "r"((a)[2]), "r"((a)[3]), "r"(b0), "r"(b1))

// ---------------- device scratch ----------------
__device__ int g_decisions[BATCH];
__device__ float g_pooled[BATCH * CIN];
// weights, tap-major fp16 pairs: [e][t][co][ci/2] u32
__device__ __align__(256) uint32_t g_wh[(size_t)NE * 9 * COUT * 128];          // 9.4 MB
// padded+shifted X fp16 pairs: [i][dx 3][ci][34 rows][16 px-pairs] u32
__device__ __align__(256) uint32_t g_xp[(size_t)BATCH * 3 * CIN * 34 * 16];    // 26.7 MB

__device__ __forceinline__ uint32_t pack2(float v0, float v1) {
    __half h0 = __float2half_rn(v0), h1 = __float2half_rn(v1);
    return ((uint32_t)__half_as_ushort(h1) << 16) | __half_as_ushort(h0);
}

// ---------------- kernel 1: fused prep (xpad + weight reorder + pooling) ----
// blocks [0,4096): xpad + pooled sum for (i = b>>8, ci = b&255)
// blocks [4096,6144): weight row (e*256+co) -> [e][t][co][ci]
__global__ void prep_kernel(const float* __restrict__ x, const float* __restrict__ we) {
    __shared__ float s[2304];
    __shared__ float sRed[8];
    const int b = blockIdx.x, tid = threadIdx.x;
    if (b < 4096) {
        const int i = b >> 8, ci = b & 255;
        const float* src = x + ((size_t)i * CIN + ci) * HW;
        for (int k = tid; k < 1024; k += 256) s[k] = src[k];
        __syncthreads();

        // pooled mean (whole block reduces s[0..1023])
        {
            float v = s[tid] + s[tid + 256] + s[tid + 512] + s[tid + 768];
            #pragma unroll
            for (int o = 16; o > 0; o >>= 1) v += __shfl_xor_sync(0xffffffffu, v, o);
            if ((tid & 31) == 0) sRed[tid >> 5] = v;
            __syncthreads();
            if (tid == 0) {
                float t = 0.f;
                #pragma unroll
                for (int w = 0; w < 8; w++) t += sRed[w];
                g_pooled[i * CIN + ci] = t * (1.0f / HW);
            }
        }

        uint32_t* dst = g_xp + (((size_t)i * 3 * CIN + ci) * 34) * 16;  // + dxs*CIN*34*16
        for (int idx = tid; idx < 3 * 34 * 16; idx += 256) {
            int xp = (idx & 15) * 2;
            int rest = idx >> 4;
            int yy = rest % 34;
            int dxs = rest / 34;
            float v0 = 0.f, v1 = 0.f;
            if (yy >= 1 && yy <= 32) {
                int sx0 = xp + dxs - 1;
                if ((unsigned)sx0 < 32u)       v0 = s[(yy - 1) * 32 + sx0];
                if ((unsigned)(sx0 + 1) < 32u) v1 = s[(yy - 1) * 32 + sx0 + 1];
            }
            dst[((size_t)dxs * CIN * 34 + yy) * 16 + (idx & 15)] = pack2(v0, v1);
        }
    } else {
        const int row = b - 4096;                 // e*256+co
        const int e = row >> 8, co = row & 255;
        const float* src = we + (size_t)row * 2304;  // [ci][3][3]
        for (int k = tid; k < 2304; k += 256) s[k] = src[k];
        __syncthreads();
        for (int idx = tid; idx < 9 * 128; idx += 256) {
            int t = idx >> 7, cip = idx & 127;
            int ci0 = cip * 2;
            g_wh[((size_t)(e * 9 + t) * COUT + co) * 128 + cip] =
                pack2(s[ci0 * 9 + t], s[(ci0 + 1) * 9 + t]);
        }
    }
}

// ---------------- kernel 2: router finish (logits + argmax), 1 block ---------
__global__ void router_finish_kernel(const float* __restrict__ wc,
                                     const float* __restrict__ bc) {
    __shared__ float sLog[BATCH][NE];
    const int tid = threadIdx.x;               // 128 threads: b = tid>>3, e = tid&7
    const int b = tid >> 3, e = tid & 7;
    const float* p = g_pooled + b * CIN;
    const float* w = wc + e * CIN;
    float sum = 0.f;
    #pragma unroll 8
    for (int k = 0; k < CIN; k++) sum += p[k] * w[k];
    sLog[b][e] = sum + bc[e];
    __syncthreads();
    if (tid < BATCH) {
        float best = sLog[tid][0]; int bi = 0;
        #pragma unroll
        for (int ee = 1; ee < NE; ee++)
            if (sLog[tid][ee] > best) { best = sLog[tid][ee]; bi = ee; }
        g_decisions[tid] = bi;
    }
}

// ---------------- kernel 3: HMMA implicit GEMM (no im2col tensor) ----------------
// D[co][pix] = sum_t W_t[co][ci] * Xshift_t[ci][pix]
// grid (4 px-tiles of 256, 2 co-tiles of 128, 128 pairs), 256 threads.
__global__ void __launch_bounds__(256, 1)
gemm_kernel(const float* __restrict__ be, float* __restrict__ out) {
    extern __shared__ __align__(16) char dynraw[];
    char* dyn = (char*)(((uintptr_t)dynraw + 1023) & ~(uintptr_t)1023);
    const uint32_t dynu = smem_u32(dyn);

    __shared__ int sDec[BATCH];
    const int tid = threadIdx.x;
    const int ntile = blockIdx.x, mtile = blockIdx.y, pair = blockIdx.z;
    const int i = pair & 15, e = pair >> 4;

    if (tid < BATCH) sDec[tid] = g_decisions[tid];
    __syncthreads();
    bool need = false;
    #pragma unroll
    for (int j = 0; j < BATCH; j++) need |= (sDec[j] == e);
    if (!need) return;

    const int lane = tid & 31, wid = tid >> 5;
    const int wm = wid & 1, wn = wid >> 1;
    const int y0 = ntile << 3;                    // first image row of px tile

    // A gmem->smem mapping (per 16KB half: 128 co rows x 128B)
    const int ldRow = tid >> 3, ldc = tid & 7;
    const uint32_t stsOffA = SWZ(ldRow * 128 + ldc * 16);

    float acc[4][8][4];
    #pragma unroll
    for (int ma = 0; ma < 4; ma++)
        #pragma unroll
        for (int na = 0; na < 8; na++)
            #pragma unroll
            for (int c = 0; c < 4; c++) acc[ma][na][c] = 0.f;

    // fragment address constants
    const uint32_t aFragBase = (uint32_t)((wm * 64 + (lane & 15)) * 128 + ((lane >> 4) << 4));
    const uint32_t bRowBase = (uint32_t)((lane & 15) * 512);
    uint32_t bConst[4];
    #pragma unroll
    for (int pb = 0; pb < 4; pb++)
        bConst[pb] = (uint32_t)((((wn << 6) + (pb << 4) + ((lane >> 4) << 3)) << 1)
                                ^ ((lane & 7) << 4));

    // stage loader: chunk it (t = it>>1, ci-half ch = it&1) into stage buf
    auto load_stage = [&](int buf, int it) {
        const int t = it >> 1, ch = it & 1;
        const int ty = t / 3, tx = t % 3;
        const uint32_t st = dynu + buf * STAGE;
        // A: [co 128][ci 128] as 2 halves of [co 128][64ci=128B]
        const uint32_t* wrow = g_wh + ((size_t)(e * 9 + t) * COUT + (mtile << 7) + ldRow) * 128
                               + (ch << 6) + ldc * 4;
        #pragma unroll
        for (int h = 0; h < 2; h++)
            #pragma unroll
            for (int jj = 0; jj < 4; jj++)
                CP_ASYNC16(st + h * 16384 + stsOffA + jj * 32 * 128,
                           (const char*)(wrow + h * 32 + jj * 32 * 128));
        // B: [ci 128][px 256] as 2 halves of [ci 64][512B]; per ci one contiguous 512B
        const size_t bRow64 = ((size_t)(i * 3 + tx) * CIN + (ch << 7)) * 34 + y0 + ty;  // 64B units
        #pragma unroll
        for (int h = 0; h < 2; h++) {
            #pragma unroll
            for (int jj = 0; jj < 8; jj++) {
                const int ciL = jj * 8 + wid;
                const uint32_t dst = st + 32768 + h * 32768 + ciL * 512
                                     + (((uint32_t)lane << 4) ^ ((uint32_t)wid << 4));
                const char* src = (const char*)g_xp
                                  + ((bRow64 + (size_t)(h * 64 + ciL) * 34) << 6) + lane * 16;
                CP_ASYNC16(dst, src);
            }
        }
    };

    load_stage(0, 0);
    CP_COMMIT();

    #pragma unroll 1
    for (int it = 0; it < NCHUNK; ++it) {
        CP_WAIT0();
        __syncthreads();
        if (it + 1 < NCHUNK) { load_stage((it + 1) & 1, it + 1); CP_COMMIT(); }

        const uint32_t bA = dynu + (it & 1) * STAGE;
        const uint32_t bB = bA + 32768;
        #pragma unroll
        for (int s = 0; s < 8; s++) {
            const uint32_t hA = bA + (s >> 2) * 16384;
            const uint32_t hB = bB + (s >> 2) * 32768 + ((s & 3) * 16) * 512 + bRowBase;
            uint32_t af[4][4], bf[4][4];
            #pragma unroll
            for (int ma = 0; ma < 4; ma++)
                LDSM_X4(af[ma], hA + SWZ(aFragBase + ma * 2048 + (s & 3) * 32));
            #pragma unroll
            for (int pb = 0; pb < 4; pb++)
                LDSM_X4T(bf[pb], hB + bConst[pb]);
            #pragma unroll
            for (int ma = 0; ma < 4; ma++)
                #pragma unroll
                for (int pb = 0; pb < 4; pb++) {
                    MMA16816(acc[ma][pb * 2],     af[ma], bf[pb][0], bf[pb][1]);
                    MMA16816(acc[ma][pb * 2 + 1], af[ma], bf[pb][2], bf[pb][3]);
                }
        }
    }

    // ---------------- epilogue: bias + relu, broadcast to matching j ----------
    const int coBase = (mtile << 7) + wm * 64 + (lane >> 2);
    const int pixBase = (ntile << 8) + wn * 64 + 2 * (lane & 3);
    float bias0[4], bias1[4];
    #pragma unroll
    for (int ma = 0; ma < 4; ma++) {
        bias0[ma] = be[(e << 8) + coBase + ma * 16];
        bias1[ma] = be[(e << 8) + coBase + ma * 16 + 8];
    }
    #pragma unroll 1
    for (int j = 0; j < BATCH; j++) {
        if (sDec[j] != e) continue;
        float* ob = out + ((size_t)(j * BATCH + i) << 18);   // *256*1024
        #pragma unroll
        for (int ma = 0; ma < 4; ma++) {
            const int co = coBase + ma * 16;
            #pragma unroll
            for (int na = 0; na < 8; na++) {
                const int pix = pixBase + na * 8;
                float2 v0, v1;
                v0.x = fmaxf(acc[ma][na][0] + bias0[ma], 0.f);
                v0.y = fmaxf(acc[ma][na][1] + bias0[ma], 0.f);
                v1.x = fmaxf(acc[ma][na][2] + bias1[ma], 0.f);
                v1.y = fmaxf(acc[ma][na][3] + bias1[ma], 0.f);
                *(float2*)(ob + (size_t)co * HW + pix)       = v0;
                *(float2*)(ob + (size_t)(co + 8) * HW + pix) = v1;
            }
        }
    }
}

// ---------------------------------------------------------------------------
extern "C" void kernel_launch(void* const* d_in, const int* in_sizes, int n_in,
                              void* d_out, int out_size) {
    const float* x  = (const float*)d_in[0];
    const float* wc = (const float*)d_in[1];
    const float* bc = (const float*)d_in[2];
    const float* we = (const float*)d_in[3];
    const float* be = (const float*)d_in[4];
    float* out = (float*)d_out;

    static int smemSet = 0;
    if (!smemSet) {
        cudaFuncSetAttribute(gemm_kernel, cudaFuncAttributeMaxDynamicSharedMemorySize,
                             SMEM_TOTAL);
        smemSet = 1;
    }

    prep_kernel<<<4096 + NE * COUT, 256>>>(x, we);
    router_finish_kernel<<<1, 128>>>(wc, bc);
    gemm_kernel<<<dim3(4, 2, BATCH * NE), 256, SMEM_TOTAL>>>(be, out);
}

// round 8
// speedup vs baseline: 10.9667x; 1.0491x over previous
#include <cuda_runtime.h>
#include <cuda_fp16.h>
#include <stdint.h>

#define BATCH 16
#define CIN   256
#define COUT  256
#define HW    1024
#define NE    8
#define NCHUNK 36             /* 9 taps * 4 ci-quarters of 64 */
#define STAGE  32768          /* A 16KB + B 16KB */
#define NSTAGE 3
#define SMEM_TOTAL (NSTAGE * STAGE + 1024)

// ---------------- helpers ----------------
__device__ __forceinline__ uint32_t smem_u32(const void* p) {
    uint32_t a;
    asm("{ .reg .u64 t; cvta.to.shared.u64 t, %1; cvt.u32.u64 %0, t; }" : "=r"(a) : "l"(p));
    return a;
}
#define SWZ(off) ((off) ^ (((off) >> 3) & 0x70))

#define CP_ASYNC16(dst, src) \
    asm volatile("cp.async.cg.shared.global [%0], [%1], 16;" :: "r"(dst), "l"(src) : "memory")
#define CP_COMMIT() asm volatile("cp.async.commit_group;" ::: "memory")
#define CP_WAIT1()  asm volatile("cp.async.wait_group 1;" ::: "memory")

#define LDSM_X4(r, addr) \
    asm volatile("ldmatrix.sync.aligned.m8n8.x4.shared.b16 {%0,%1,%2,%3}, [%4];" \
        : "=r"((r)[0]), "=r"((r)[1]), "=r"((r)[2]), "=r"((r)[3]) : "r"(addr))
#define LDSM_X4T(r, addr) \
    asm volatile("ldmatrix.sync.aligned.m8n8.x4.trans.shared.b16 {%0,%1,%2,%3}, [%4];" \
        : "=r"((r)[0]), "=r"((r)[1]), "=r"((r)[2]), "=r"((r)[3]) : "r"(addr))

#define MMA16816(d, a, b0, b1) \
    asm volatile("mma.sync.aligned.m16n8k16.row.col.f32.f16.f16.f32 " \
        "{%0,%1,%2,%3}, {%4,%5,%6,%7}, {%8,%9}, {%0,%1,%2,%3};" \
        : "+f"((d)[0]), "+f"((d)[1]), "+f"((d)[2]), "+f"((d)[3]) \
        : "r"((a)[0]), "r"((a)[1]), "r"((a)[2]), "r"((a)[3]), "r"(b0), "r"(b1))

// ---------------- device scratch ----------------
__device__ int g_decisions[BATCH];
__device__ float g_pooled[BATCH * CIN];
// weights, tap-major fp16 pairs: [e][t][co][ci/2] u32
__device__ __align__(256) uint32_t g_wh[(size_t)NE * 9 * COUT * 128];          // 9.4 MB
// padded+shifted X fp16 pairs: [i][dx 3][ci][34 rows][16 px-pairs] u32
__device__ __align__(256) uint32_t g_xp[(size_t)BATCH * 3 * CIN * 34 * 16];    // 26.7 MB

__device__ __forceinline__ uint32_t pack2(float v0, float v1) {
    __half h0 = __float2half_rn(v0), h1 = __float2half_rn(v1);
    return ((uint32_t)__half_as_ushort(h1) << 16) | __half_as_ushort(h0);
}

// ---------------- kernel 1: fused prep (xpad + weight reorder + pooling) ----
__global__ void prep_kernel(const float* __restrict__ x, const float* __restrict__ we) {
    __shared__ float s[2304];
    __shared__ float sRed[8];
    const int b = blockIdx.x, tid = threadIdx.x;
    if (b < 4096) {
        const int i = b >> 8, ci = b & 255;
        const float* src = x + ((size_t)i * CIN + ci) * HW;
        for (int k = tid; k < 1024; k += 256) s[k] = src[k];
        __syncthreads();
        {
            float v = s[tid] + s[tid + 256] + s[tid + 512] + s[tid + 768];
            #pragma unroll
            for (int o = 16; o > 0; o >>= 1) v += __shfl_xor_sync(0xffffffffu, v, o);
            if ((tid & 31) == 0) sRed[tid >> 5] = v;
            __syncthreads();
            if (tid == 0) {
                float t = 0.f;
                #pragma unroll
                for (int w = 0; w < 8; w++) t += sRed[w];
                g_pooled[i * CIN + ci] = t * (1.0f / HW);
            }
        }
        uint32_t* dst = g_xp + (((size_t)i * 3 * CIN + ci) * 34) * 16;
        for (int idx = tid; idx < 3 * 34 * 16; idx += 256) {
            int xp = (idx & 15) * 2;
            int rest = idx >> 4;
            int yy = rest % 34;
            int dxs = rest / 34;
            float v0 = 0.f, v1 = 0.f;
            if (yy >= 1 && yy <= 32) {
                int sx0 = xp + dxs - 1;
                if ((unsigned)sx0 < 32u)       v0 = s[(yy - 1) * 32 + sx0];
                if ((unsigned)(sx0 + 1) < 32u) v1 = s[(yy - 1) * 32 + sx0 + 1];
            }
            dst[((size_t)dxs * CIN * 34 + yy) * 16 + (idx & 15)] = pack2(v0, v1);
        }
    } else {
        const int row = b - 4096;                 // e*256+co
        const int e = row >> 8, co = row & 255;
        const float* src = we + (size_t)row * 2304;
        for (int k = tid; k < 2304; k += 256) s[k] = src[k];
        __syncthreads();
        for (int idx = tid; idx < 9 * 128; idx += 256) {
            int t = idx >> 7, cip = idx & 127;
            int ci0 = cip * 2;
            g_wh[((size_t)(e * 9 + t) * COUT + co) * 128 + cip] =
                pack2(s[ci0 * 9 + t], s[(ci0 + 1) * 9 + t]);
        }
    }
}

// ---------------- kernel 2: router finish ----------------
__global__ void router_finish_kernel(const float* __restrict__ wc,
                                     const float* __restrict__ bc) {
    __shared__ float sLog[BATCH][NE];
    const int tid = threadIdx.x;
    const int b = tid >> 3, e = tid & 7;
    const float* p = g_pooled + b * CIN;
    const float* w = wc + e * CIN;
    float sum = 0.f;
    #pragma unroll 8
    for (int k = 0; k < CIN; k++) sum += p[k] * w[k];
    sLog[b][e] = sum + bc[e];
    __syncthreads();
    if (tid < BATCH) {
        float best = sLog[tid][0]; int bi = 0;
        #pragma unroll
        for (int ee = 1; ee < NE; ee++)
            if (sLog[tid][ee] > best) { best = sLog[tid][ee]; bi = ee; }
        g_decisions[tid] = bi;
    }
}

// ---------------- kernel 3: HMMA implicit GEMM, 128 thr, 2 CTAs/SM ----------
// CTA tile 128co x 128px; 4 warps of 64x64. K-chunk 64, 3-stage cp.async.
// grid (8 px-tiles of 128, 2 co-tiles of 128, 128 pairs).
__global__ void __launch_bounds__(128, 2)
gemm_kernel(const float* __restrict__ be, float* __restrict__ out) {
    extern __shared__ __align__(16) char dynraw[];
    char* dyn = (char*)(((uintptr_t)dynraw + 1023) & ~(uintptr_t)1023);
    const uint32_t dynu = smem_u32(dyn);

    __shared__ int sDec[BATCH];
    const int tid = threadIdx.x;
    const int ntile = blockIdx.x, mtile = blockIdx.y, pair = blockIdx.z;
    const int i = pair & 15, e = pair >> 4;

    if (tid < BATCH) sDec[tid] = g_decisions[tid];
    __syncthreads();
    bool need = false;
    #pragma unroll
    for (int j = 0; j < BATCH; j++) need |= (sDec[j] == e);
    if (!need) return;

    const int lane = tid & 31, wid = tid >> 5;
    const int wm = wid & 1, wn = wid >> 1;     // 2x2 warp grid, 64co x 64px each
    const int y0 = ntile << 2;                 // first image row of 128-px tile

    float acc[4][8][4];
    #pragma unroll
    for (int ma = 0; ma < 4; ma++)
        #pragma unroll
        for (int na = 0; na < 8; na++)
            #pragma unroll
            for (int c = 0; c < 4; c++) acc[ma][na][c] = 0.f;

    // A fragment base (within 16KB A region): 128B rows, SW128 swizzle
    const uint32_t aFragBase = (uint32_t)((wm * 64 + (lane & 15)) * 128 + ((lane >> 4) << 4));
    // B fragment addresses (within 16KB B region): 64 ci rows x 256B, XOR swizzle
    uint32_t bAddr[4];
    #pragma unroll
    for (int pb = 0; pb < 4; pb++) {
        uint32_t p = (uint32_t)(wn * 128 + pb * 32 + ((lane >> 4) << 4));  // px byte off
        bAddr[pb] = (uint32_t)((lane & 15) * 256) + ((((p >> 4) ^ (lane & 7)) << 4));
    }

    // gmem->smem maps
    const int ldcA = tid & 7;                   // A: 8 chunks of 16B per 128B row
    const int coL0 = tid >> 3;                  // +16 per round (8 rounds)
    const int ldcB = tid & 15;                  // B: 16 chunks of 16B per 256B row
    const int ciL0 = tid >> 4;                  // +8 per round (8 rounds)
    const uint32_t dstB0 = (uint32_t)(((ldcB ^ ciL0) & 15) << 4);  // note ciL0<8

    auto load_stage = [&](int buf, int it) {
        const int t = it >> 2, qc = it & 3;
        const int ty = t / 3, tx = t % 3;
        const uint32_t st = dynu + buf * STAGE;
        // A: [128 co][64 ci = 128B]
        const uint32_t* wrow = g_wh + ((size_t)(e * 9 + t) * COUT + (mtile << 7) + coL0) * 128
                               + (qc << 5) + ldcA * 4;
        #pragma unroll
        for (int r = 0; r < 8; r++)
            CP_ASYNC16(st + SWZ((coL0 + r * 16) * 128 + ldcA * 16),
                       (const char*)(wrow + (size_t)r * 16 * 128));
        // B: [64 ci][256B = 128px over 4 image rows], contiguous per ci
        const size_t bRow64 = ((size_t)(i * 3 + tx) * CIN + (qc << 6) + ciL0) * 34 + y0 + ty;
        #pragma unroll
        for (int r = 0; r < 8; r++) {
            const int ci = ciL0 + r * 8;
            CP_ASYNC16(st + 16384 + ci * 256 + dstB0,
                       (const char*)g_xp + ((bRow64 + (size_t)r * 8 * 34) << 6) + ldcB * 16);
        }
    };

    load_stage(0, 0); CP_COMMIT();
    load_stage(1, 1); CP_COMMIT();

    int buf = 0, pfbuf = 2;
    #pragma unroll 1
    for (int it = 0; it < NCHUNK; ++it) {
        CP_WAIT1();
        __syncthreads();
        if (it + 2 < NCHUNK) { load_stage(pfbuf, it + 2); CP_COMMIT(); }

        const uint32_t bA = dynu + buf * STAGE;
        const uint32_t bB = bA + 16384;
        #pragma unroll
        for (int s = 0; s < 4; s++) {
            uint32_t af[4][4], bf[4][4];
            #pragma unroll
            for (int ma = 0; ma < 4; ma++)
                LDSM_X4(af[ma], bA + SWZ(aFragBase + ma * 2048 + s * 32));
            #pragma unroll
            for (int pb = 0; pb < 4; pb++)
                LDSM_X4T(bf[pb], bB + s * 4096 + bAddr[pb]);
            #pragma unroll
            for (int ma = 0; ma < 4; ma++)
                #pragma unroll
                for (int pb = 0; pb < 4; pb++) {
                    MMA16816(acc[ma][pb * 2],     af[ma], bf[pb][0], bf[pb][1]);
                    MMA16816(acc[ma][pb * 2 + 1], af[ma], bf[pb][2], bf[pb][3]);
                }
        }
        buf = (buf == 2) ? 0 : buf + 1;
        pfbuf = (pfbuf == 2) ? 0 : pfbuf + 1;
    }

    // ---------------- epilogue ----------------
    const int coBase = (mtile << 7) + wm * 64 + (lane >> 2);
    const int pixBase = (ntile << 7) + wn * 64 + 2 * (lane & 3);
    float bias0[4], bias1[4];
    #pragma unroll
    for (int ma = 0; ma < 4; ma++) {
        bias0[ma] = be[(e << 8) + coBase + ma * 16];
        bias1[ma] = be[(e << 8) + coBase + ma * 16 + 8];
    }
    #pragma unroll 1
    for (int j = 0; j < BATCH; j++) {
        if (sDec[j] != e) continue;
        float* ob = out + ((size_t)(j * BATCH + i) << 18);
        #pragma unroll
        for (int ma = 0; ma < 4; ma++) {
            const int co = coBase + ma * 16;
            #pragma unroll
            for (int na = 0; na < 8; na++) {
                const int pix = pixBase + na * 8;
                float2 v0, v1;
                v0.x = fmaxf(acc[ma][na][0] + bias0[ma], 0.f);
                v0.y = fmaxf(acc[ma][na][1] + bias0[ma], 0.f);
                v1.x = fmaxf(acc[ma][na][2] + bias1[ma], 0.f);
                v1.y = fmaxf(acc[ma][na][3] + bias1[ma], 0.f);
                *(float2*)(ob + (size_t)co * HW + pix)       = v0;
                *(float2*)(ob + (size_t)(co + 8) * HW + pix) = v1;
            }
        }
    }
}

// ---------------------------------------------------------------------------
extern "C" void kernel_launch(void* const* d_in, const int* in_sizes, int n_in,
                              void* d_out, int out_size) {
    const float* x  = (const float*)d_in[0];
    const float* wc = (const float*)d_in[1];
    const float* bc = (const float*)d_in[2];
    const float* we = (const float*)d_in[3];
    const float* be = (const float*)d_in[4];
    float* out = (float*)d_out;

    static int smemSet = 0;
    if (!smemSet) {
        cudaFuncSetAttribute(gemm_kernel, cudaFuncAttributeMaxDynamicSharedMemorySize,
                             SMEM_TOTAL);
        smemSet = 1;
    }

    prep_kernel<<<4096 + NE * COUT, 256>>>(x, we);
    router_finish_kernel<<<1, 128>>>(wc, bc);
    gemm_kernel<<<dim3(8, 2, BATCH * NE), 128, SMEM_TOTAL>>>(be, out);
}